// round 1
// baseline (speedup 1.0000x reference)
#include <cuda_runtime.h>
#include <cstdint>

// Problem constants
#define WIDTH      1000
#define HEIGHT     1000
#define PATCH      5
#define PPW        (WIDTH / PATCH)        // 200 patches per row
#define NUM_TERMS  10
#define NPIX       (WIDTH * HEIGHT)       // 1,000,000
#define NGROUP     (NPIX / PATCH)         // 200,000 5-pixel groups

// One thread per 5 consecutive pixels. Since WIDTH % PATCH == 0, a 5-aligned
// group of pixels always lies inside ONE row of ONE patch, so the 60-float
// coefficient block is loaded once (15x LDG.128) and reused for 5 pixels.
__global__ __launch_bounds__(256)
void ts_approx_kernel(const float* __restrict__ pix,     // [NPIX, 2]
                      const float* __restrict__ coef,    // [NPATCH, 3, 10, 2]
                      const float* __restrict__ bias,    // [NPATCH, 3]
                      float* __restrict__ out)           // [3, NPIX]
{
    int g = blockIdx.x * blockDim.x + threadIdx.x;
    if (g >= NGROUP) return;

    const int n0  = g * PATCH;
    const int row = n0 / WIDTH;
    const int col = n0 - row * WIDTH;
    const int patch = (row / PATCH) * PPW + (col / PATCH);

    // 60 coefficient floats, 16B-aligned (240 bytes/patch)
    float4 cf4[15];
    const float4* cp = reinterpret_cast<const float4*>(coef + (size_t)patch * 60);
#pragma unroll
    for (int i = 0; i < 15; i++) cf4[i] = __ldg(cp + i);
    const float* c = reinterpret_cast<const float*>(cf4);
    // layout: c[ch*20 + t*2 + d], d=0 -> x-coef, d=1 -> y-coef

    const float b0 = __ldg(bias + patch * 3 + 0);
    const float b1 = __ldg(bias + patch * 3 + 1);
    const float b2 = __ldg(bias + patch * 3 + 2);

    const float2* pp = reinterpret_cast<const float2*>(pix);

    float r0[PATCH], r1[PATCH], r2[PATCH];

#pragma unroll
    for (int j = 0; j < PATCH; j++) {
        const float2 p = __ldg(pp + n0 + j);
        const float x = p.x, y = p.y;

        float a0 = b0, a1 = b1, a2 = b2;
        float xp = 1.0f, yp = 1.0f;
#pragma unroll
        for (int t = 0; t < NUM_TERMS; t++) {
            a0 = fmaf(c[      t * 2 + 0], xp, a0);
            a0 = fmaf(c[      t * 2 + 1], yp, a0);
            a1 = fmaf(c[20 +  t * 2 + 0], xp, a1);
            a1 = fmaf(c[20 +  t * 2 + 1], yp, a1);
            a2 = fmaf(c[40 +  t * 2 + 0], xp, a2);
            a2 = fmaf(c[40 +  t * 2 + 1], yp, a2);
            xp *= x;
            yp *= y;
        }
        r0[j] = a0; r1[j] = a1; r2[j] = a2;
    }

    // Coalesced per-channel streams: thread g owns floats [n0, n0+5)
#pragma unroll
    for (int j = 0; j < PATCH; j++) out[            n0 + j] = r0[j];
#pragma unroll
    for (int j = 0; j < PATCH; j++) out[    NPIX +  n0 + j] = r1[j];
#pragma unroll
    for (int j = 0; j < PATCH; j++) out[2 * NPIX +  n0 + j] = r2[j];
}

extern "C" void kernel_launch(void* const* d_in, const int* in_sizes, int n_in,
                              void* d_out, int out_size)
{
    const float* pix  = (const float*)d_in[0];   // [1e6, 2]
    const float* coef = (const float*)d_in[1];   // [40000, 3, 10, 2]
    const float* bias = (const float*)d_in[2];   // [40000, 3]
    float* out = (float*)d_out;                  // [3, 1e6]

    const int threads = 256;
    const int blocks  = (NGROUP + threads - 1) / threads;   // 782
    ts_approx_kernel<<<blocks, threads>>>(pix, coef, bias, out);
}

// round 10
// speedup vs baseline: 1.5970x; 1.5970x over previous
#include <cuda_runtime.h>
#include <cstdint>

// Problem constants
#define WIDTH      1000
#define HEIGHT     1000
#define PATCH      5
#define PPW        (WIDTH / PATCH)        // 200 patches per patch-row (band)
#define NUM_TERMS  10
#define NPIX       (WIDTH * HEIGHT)       // 1,000,000
#define NBANDS     (HEIGHT / PATCH)       // 200 bands
#define SEGS       8                      // segments per band
#define PPB        (PPW / SEGS)           // 25 patches per block
#define CPB        (PPB * PATCH)          // 125 columns (pixels) per block row
#define THREADS    128

// Block handles a tile of 25 patches (125 cols x 5 rows = 625 pixels).
// All global traffic is staged through shared memory fully coalesced;
// per-thread compute (q = patch, r = row; q fastest across lanes) reads
// smem conflict-free.
__global__ void __launch_bounds__(THREADS, 8)
ts_approx_kernel(const float* __restrict__ pix,     // [NPIX, 2]
                 const float* __restrict__ coef,    // [NPATCH, 3, 10, 2]
                 const float* __restrict__ bias,    // [NPATCH, 3]
                 float* __restrict__ out)           // [3, NPIX]
{
    __shared__ float4 s_coef4[PPB * 15];        // 25 patches * 60 floats (6000 B)
    __shared__ float2 s_pix[PATCH * CPB];       // 5 rows * 125 float2   (5000 B)
    __shared__ float  s_bias[PPB * 3];          //                        (300 B)
    __shared__ float  s_out[3 * PATCH * CPB];   // 3ch * 5 rows * 125    (7500 B)

    const int tid  = threadIdx.x;
    const int band = blockIdx.y;          // [0, 200)
    const int seg  = blockIdx.x;          // [0, 8)
    const int P0   = band * PPW + seg * PPB;        // first patch id
    const int col0 = seg * CPB;                     // first pixel column
    const int row0 = band * PATCH;                  // first pixel row

    // ---- Stage 1: coalesced cooperative loads into smem ----
    {
        const float4* csrc = reinterpret_cast<const float4*>(coef + (size_t)P0 * 60);
#pragma unroll
        for (int i = tid; i < PPB * 15; i += THREADS)   // 375 float4s
            s_coef4[i] = __ldg(csrc + i);

        const float2* psrc = reinterpret_cast<const float2*>(pix);
#pragma unroll
        for (int r = 0; r < PATCH; r++)
            if (tid < CPB)
                s_pix[r * CPB + tid] = __ldg(psrc + (size_t)(row0 + r) * WIDTH + col0 + tid);

        if (tid < PPB * 3)
            s_bias[tid] = __ldg(bias + P0 * 3 + tid);
    }
    __syncthreads();

    // ---- Stage 2: compute (125 active threads; q fastest across lanes) ----
    if (tid < PPB * PATCH) {
        const int q = tid % PPB;          // [0, 25)  patch-in-block (lane-fast)
        const int r = tid / PPB;          // [0, 5)   row-in-patch

        // pixel coords for this (patch, row): 5 consecutive columns.
        // Lane-to-lane smem stride = 5 float2 = 10 words -> conflict-free.
        float x[PATCH], y[PATCH];
#pragma unroll
        for (int j = 0; j < PATCH; j++) {
            const float2 p = s_pix[r * CPB + q * PATCH + j];
            x[j] = p.x; y[j] = p.y;
        }

        const float* cpat = reinterpret_cast<const float*>(s_coef4 + q * 15);

#pragma unroll
        for (int ch = 0; ch < 3; ch++) {
            const float* c = cpat + ch * 20;   // c[2t]=x-coef, c[2t+1]=y-coef
            const float  b = s_bias[q * 3 + ch];
#pragma unroll
            for (int j = 0; j < PATCH; j++) {
                float hx = c[18];
                float hy = c[19];
#pragma unroll
                for (int t = 8; t >= 0; t--) {
                    hx = fmaf(hx, x[j], c[2 * t + 0]);
                    hy = fmaf(hy, y[j], c[2 * t + 1]);
                }
                s_out[(ch * PATCH + r) * CPB + q * PATCH + j] = (hx + hy) + b;
            }
        }
    }
    __syncthreads();

    // ---- Stage 3: coalesced flush (15 contiguous 125-float segments) ----
    if (tid < CPB) {
#pragma unroll
        for (int ch = 0; ch < 3; ch++)
#pragma unroll
            for (int r = 0; r < PATCH; r++)
                out[(size_t)ch * NPIX + (size_t)(row0 + r) * WIDTH + col0 + tid] =
                    s_out[(ch * PATCH + r) * CPB + tid];
    }
}

extern "C" void kernel_launch(void* const* d_in, const int* in_sizes, int n_in,
                              void* d_out, int out_size)
{
    const float* pix  = (const float*)d_in[0];   // [1e6, 2]
    const float* coef = (const float*)d_in[1];   // [40000, 3, 10, 2]
    const float* bias = (const float*)d_in[2];   // [40000, 3]
    float* out = (float*)d_out;                  // [3, 1e6]

    dim3 grid(SEGS, NBANDS);                     // 8 x 200 = 1600 blocks
    ts_approx_kernel<<<grid, THREADS>>>(pix, coef, bias, out);
}